// round 5
// baseline (speedup 1.0000x reference)
#include <cuda_runtime.h>
#include <math.h>

#define NBOARD 13
#define SN 169
#define NG 2048
#define NT 384           // 2 halves x 192
#define EPSV 1e-5f
#define LSMIN -5.0f
#define LSMAX 2.0f
#define TM 16            // rows per MLP block

typedef unsigned long long ull;

__device__ __forceinline__ ull pk2(float x, float y) {
    ull r; asm("mov.b64 %0, {%1,%2};" : "=l"(r) : "f"(x), "f"(y)); return r;
}
__device__ __forceinline__ float2 upk2(ull a) {
    float2 v; asm("mov.b64 {%0,%1}, %2;" : "=f"(v.x), "=f"(v.y) : "l"(a)); return v;
}
__device__ __forceinline__ ull ffma2(ull a, ull b, ull c) {
    ull d; asm("fma.rn.f32x2 %0, %1, %2, %3;" : "=l"(d) : "l"(a), "l"(b), "l"(c)); return d;
}
__device__ __forceinline__ ull fadd2(ull a, ull b) {
    ull d; asm("add.rn.f32x2 %0, %1, %2;" : "=l"(d) : "l"(a), "l"(b)); return d;
}
__device__ __forceinline__ ull fmul2(ull a, ull b) {
    ull d; asm("mul.rn.f32x2 %0, %1, %2;" : "=l"(d) : "l"(a), "l"(b)); return d;
}

__device__ float g_pooled[NG * 72];

#define RS 74            // row stride (floats) for h and stage
#define RSU 37           // row stride in ull

struct __align__(16) Smem {
    float wc3[36 * 72];
    float wr2[36 * 72];
    float wc2[18 * 36];
    float wr1[18 * 36];
    float wc1p[18 * 20];
    float bc1[18], bc2[36], bc3[72];
    float br1[36], br2[72];
    float g1v[18], be1v[18], a1v[18];
    float g2v[36], be2v[36], a2v[36];
    float g3v[72], be3v[72], a3v[72];
    float embs[3 * 18];
    float redP[360], redQ[360];
    float redS[72], redC[72];
    float dis[170];
    float stage[SN * RS];
    float h[SN * RS];
};

__device__ __forceinline__ void cp_sm(float* dst, const float* src, int n, int t) {
    for (int i = t; i < n; i += NT) dst[i] = src[i];
}

// striped stats over stage: Wf features x (360/Wf) stripes
__device__ __forceinline__ void stats_striped(Smem& sm, int t, int Wf) {
    if (t < 360) {
        const int f = t % Wf, sI = t / Wf, step = 360 / Wf;
        float s = 0.f, s2 = 0.f;
        const float* p = sm.stage + f;
        for (int n = sI; n < SN; n += step) { float v = p[n * RS]; s += v; s2 = fmaf(v, v, s2); }
        sm.redP[t] = s; sm.redQ[t] = s2;
    }
}

__global__ void __launch_bounds__(NT) gnn_kernel(
    const int* __restrict__ x,
    const float* __restrict__ emb,
    const float* __restrict__ wc1, const float* __restrict__ bc1,
    const float* __restrict__ wc2, const float* __restrict__ bc2,
    const float* __restrict__ wc3, const float* __restrict__ bc3,
    const float* __restrict__ wr1, const float* __restrict__ br1,
    const float* __restrict__ wr2, const float* __restrict__ br2,
    const float* __restrict__ g1, const float* __restrict__ be1, const float* __restrict__ a1,
    const float* __restrict__ g2, const float* __restrict__ be2, const float* __restrict__ a2,
    const float* __restrict__ g3, const float* __restrict__ be3, const float* __restrict__ a3)
{
    extern __shared__ char smraw[];
    Smem& sm = *reinterpret_cast<Smem*>(smraw);
    const int t = threadIdx.x;
    const int g = blockIdx.x;
    const int half = t / 192;        // j-half this thread computes
    const int n = t % 192;           // node id
    const bool isNode = (n < SN);
    ull* const hU = (ull*)sm.h;
    ull* const stU = (ull*)sm.stage;
    const float invS = 1.0f / (float)SN;

    cp_sm(sm.wc3, wc3, 36 * 72, t);
    cp_sm(sm.wr2, wr2, 36 * 72, t);
    cp_sm(sm.wc2, wc2, 18 * 36, t);
    cp_sm(sm.wr1, wr1, 18 * 36, t);
    for (int i = t; i < 18 * 20; i += NT) {
        const int k = i / 20, j = i % 20;
        sm.wc1p[i] = (j < 18) ? wc1[k * 18 + j] : 0.f;
    }
    cp_sm(sm.bc1, bc1, 18, t);  cp_sm(sm.bc2, bc2, 36, t);  cp_sm(sm.bc3, bc3, 72, t);
    cp_sm(sm.br1, br1, 36, t);  cp_sm(sm.br2, br2, 72, t);
    cp_sm(sm.g1v, g1, 18, t);   cp_sm(sm.be1v, be1, 18, t); cp_sm(sm.a1v, a1, 18, t);
    cp_sm(sm.g2v, g2, 36, t);   cp_sm(sm.be2v, be2, 36, t); cp_sm(sm.a2v, a2, 36, t);
    cp_sm(sm.g3v, g3, 72, t);   cp_sm(sm.be3v, be3, 72, t); cp_sm(sm.a3v, a3, 72, t);
    cp_sm(sm.embs, emb, 3 * 18, t);

    // ---- analytic hex topology (both halves need it for gathers) ----
    int nbU[6];
    float dnb[6];
    float disn = 0.f;
    if (isNode) {
        const int r = n / NBOARD, c = n % NBOARD;
        const int drr[6] = { -1, 1, 0, 0, -1, 1 };
        const int dcc[6] = { 0, 0, -1, 1, 1, -1 };
        int deg = 1;
        #pragma unroll
        for (int j = 0; j < 6; j++) {
            int rr = r + drr[j], cc = c + dcc[j];
            if (rr >= 0 && rr < NBOARD && cc >= 0 && cc < NBOARD) {
                nbU[j] = (rr * NBOARD + cc) * RSU;
                deg++;
            } else {
                nbU[j] = n * RSU;
            }
        }
        disn = rsqrtf((float)deg);
        if (half == 0) sm.dis[n] = disn;
    }
    __syncthreads();

    if (isNode) {
        if (half == 0) {
            const int xv = x[g * SN + n];
            #pragma unroll
            for (int k = 0; k < 18; k++) sm.h[n * RS + k] = sm.embs[xv * 18 + k];
        }
        #pragma unroll
        for (int j = 0; j < 6; j++)
            dnb[j] = (nbU[j] == n * RSU) ? 0.f : sm.dis[nbU[j] / RSU];
    }
    __syncthreads();

    const ull dd = pk2(disn, disn);

    // ================= Layer 1 (18->18): half 0 only, identity residual =====
    {
        ull hkU[9], accC[9];
        if (isNode && half == 0) {
            ull aU[9];
            const ull* hr = hU + n * RSU;
            #pragma unroll
            for (int i = 0; i < 9; i++) { hkU[i] = hr[i]; aU[i] = fmul2(hkU[i], dd); }
            #pragma unroll
            for (int j = 0; j < 6; j++) {
                const ull* p = hU + nbU[j];
                const ull wj = pk2(dnb[j], dnb[j]);
                #pragma unroll
                for (int i = 0; i < 9; i++) aU[i] = ffma2(wj, p[i], aU[i]);
            }
            #pragma unroll
            for (int i = 0; i < 9; i++) aU[i] = fmul2(aU[i], dd);
            const ull* bu = (const ull*)sm.bc1;
            #pragma unroll
            for (int i = 0; i < 9; i++) accC[i] = bu[i];
            #pragma unroll 2
            for (int kp = 0; kp < 9; kp++) {
                float2 av = upk2(aU[kp]);
                #pragma unroll
                for (int s = 0; s < 2; s++) {
                    const float ak = s ? av.y : av.x;
                    const ull aa = pk2(ak, ak);
                    const float* wrow = &sm.wc1p[(2 * kp + s) * 20];
                    const ulonglong2* w2 = (const ulonglong2*)wrow;
                    #pragma unroll
                    for (int jv = 0; jv < 4; jv++) {
                        ulonglong2 w = w2[jv];
                        accC[2 * jv]     = ffma2(aa, w.x, accC[2 * jv]);
                        accC[2 * jv + 1] = ffma2(aa, w.y, accC[2 * jv + 1]);
                    }
                    accC[8] = ffma2(aa, ((const ull*)wrow)[8], accC[8]);
                }
            }
            ull* st = stU + n * RSU;
            #pragma unroll
            for (int i = 0; i < 9; i++) st[i] = accC[i];
        }
        __syncthreads();
        stats_striped(sm, t, 18);
        __syncthreads();
        if (t < 18) {
            float s = 0.f, s2 = 0.f;
            #pragma unroll
            for (int i = 0; i < 20; i++) { s += sm.redP[t + i * 18]; s2 += sm.redQ[t + i * 18]; }
            float m = s * invS;
            float af = sm.a1v[t];
            float var = s2 * invS - m * m * af * (2.0f - af);
            float S = sm.g1v[t] * rsqrtf(var + EPSV);
            sm.redS[t] = S; sm.redC[t] = sm.be1v[t] - af * m * S;
        }
        __syncthreads();
        if (isNode && half == 0) {
            const ull* Su = (const ull*)sm.redS;
            const ull* Cu = (const ull*)sm.redC;
            ull* hr = hU + n * RSU;
            #pragma unroll
            for (int i = 0; i < 9; i++)
                hr[i] = fadd2(ffma2(accC[i], Su[i], Cu[i]), hkU[i]);
        }
        __syncthreads();
    }

    // ====== Layer 2 (18->36): split-j, conv + resid in one k-loop ===========
    {
        ull accC[9], accR[9];
        if (isNode) {
            ull hkU[9], aU[9];
            const ull* hr = hU + n * RSU;
            #pragma unroll
            for (int i = 0; i < 9; i++) { hkU[i] = hr[i]; aU[i] = fmul2(hkU[i], dd); }
            #pragma unroll
            for (int j = 0; j < 6; j++) {
                const ull* p = hU + nbU[j];
                const ull wj = pk2(dnb[j], dnb[j]);
                #pragma unroll
                for (int i = 0; i < 9; i++) aU[i] = ffma2(wj, p[i], aU[i]);
            }
            #pragma unroll
            for (int i = 0; i < 9; i++) aU[i] = fmul2(aU[i], dd);
            const ull* buC = (const ull*)&sm.bc2[half * 18];
            const ull* buR = (const ull*)&sm.br1[half * 18];
            #pragma unroll
            for (int i = 0; i < 9; i++) { accC[i] = buC[i]; accR[i] = buR[i]; }
            #pragma unroll 2
            for (int kp = 0; kp < 9; kp++) {
                float2 av = upk2(aU[kp]);
                float2 hv = upk2(hkU[kp]);
                #pragma unroll
                for (int s = 0; s < 2; s++) {
                    const float ak = s ? av.y : av.x;
                    const float hk = s ? hv.y : hv.x;
                    const ull aa = pk2(ak, ak);
                    const ull hh = pk2(hk, hk);
                    const int k = 2 * kp + s;
                    const ull* wc = (const ull*)&sm.wc2[k * 36 + half * 18];
                    const ull* wr = (const ull*)&sm.wr1[k * 36 + half * 18];
                    #pragma unroll
                    for (int jv = 0; jv < 9; jv++) {
                        accC[jv] = ffma2(aa, wc[jv], accC[jv]);
                        accR[jv] = ffma2(hh, wr[jv], accR[jv]);
                    }
                }
            }
            ull* st = stU + n * RSU + half * 9;
            #pragma unroll
            for (int i = 0; i < 9; i++) st[i] = accC[i];
        }
        __syncthreads();
        stats_striped(sm, t, 36);
        __syncthreads();
        if (t < 36) {
            float s = 0.f, s2 = 0.f;
            #pragma unroll
            for (int i = 0; i < 10; i++) { s += sm.redP[t + i * 36]; s2 += sm.redQ[t + i * 36]; }
            float m = s * invS;
            float af = sm.a2v[t];
            float var = s2 * invS - m * m * af * (2.0f - af);
            float S = sm.g2v[t] * rsqrtf(var + EPSV);
            sm.redS[t] = S; sm.redC[t] = sm.be2v[t] - af * m * S;
        }
        __syncthreads();
        if (isNode) {
            const ull* Su = (const ull*)&sm.redS[half * 18];
            const ull* Cu = (const ull*)&sm.redC[half * 18];
            ull* hr = hU + n * RSU + half * 9;
            #pragma unroll
            for (int i = 0; i < 9; i++)
                hr[i] = fadd2(ffma2(accC[i], Su[i], Cu[i]), accR[i]);
        }
        __syncthreads();
    }

    // ====== Layer 3 (36->72): split-j; resid then conv, accR stays in regs ==
    {
        ull aU[18], accR[18], accC[18];
        if (isNode) {
            ull hkU[18];
            const ull* hr = hU + n * RSU;
            #pragma unroll
            for (int i = 0; i < 18; i++) { hkU[i] = hr[i]; aU[i] = fmul2(hkU[i], dd); }
            #pragma unroll
            for (int j = 0; j < 6; j++) {
                const ull* p = hU + nbU[j];
                const ull wj = pk2(dnb[j], dnb[j]);
                #pragma unroll
                for (int i = 0; i < 18; i++) aU[i] = ffma2(wj, p[i], aU[i]);
            }
            #pragma unroll
            for (int i = 0; i < 18; i++) aU[i] = fmul2(aU[i], dd);

            // residual proj: 36 inputs -> this half's 36 outputs
            const ull* buR = (const ull*)&sm.br2[half * 36];
            #pragma unroll
            for (int i = 0; i < 18; i++) accR[i] = buR[i];
            #pragma unroll 1
            for (int kp = 0; kp < 18; kp++) {
                float2 hv = upk2(hkU[kp]);
                #pragma unroll
                for (int s = 0; s < 2; s++) {
                    const float hk = s ? hv.y : hv.x;
                    const ull hh = pk2(hk, hk);
                    const ulonglong2* wr = (const ulonglong2*)&sm.wr2[(2 * kp + s) * 72 + half * 36];
                    #pragma unroll
                    for (int jv = 0; jv < 9; jv++) {
                        ulonglong2 u = wr[jv];
                        accR[2 * jv]     = ffma2(hh, u.x, accR[2 * jv]);
                        accR[2 * jv + 1] = ffma2(hh, u.y, accR[2 * jv + 1]);
                    }
                }
            }

            // conv: 36 aggregated inputs -> this half's 36 outputs
            const ull* buC = (const ull*)&sm.bc3[half * 36];
            #pragma unroll
            for (int i = 0; i < 18; i++) accC[i] = buC[i];
            #pragma unroll 1
            for (int kp = 0; kp < 18; kp++) {
                float2 av = upk2(aU[kp]);
                #pragma unroll
                for (int s = 0; s < 2; s++) {
                    const float ak = s ? av.y : av.x;
                    const ull aa = pk2(ak, ak);
                    const ulonglong2* wc = (const ulonglong2*)&sm.wc3[(2 * kp + s) * 72 + half * 36];
                    #pragma unroll
                    for (int jv = 0; jv < 9; jv++) {
                        ulonglong2 w = wc[jv];
                        accC[2 * jv]     = ffma2(aa, w.x, accC[2 * jv]);
                        accC[2 * jv + 1] = ffma2(aa, w.y, accC[2 * jv + 1]);
                    }
                }
            }
            ull* st = stU + n * RSU + half * 18;
            #pragma unroll
            for (int i = 0; i < 18; i++) st[i] = accC[i];
        }
        __syncthreads();
        stats_striped(sm, t, 72);    // single 72-wide stats round
        __syncthreads();
        if (t < 72) {
            float s = 0.f, s2 = 0.f;
            #pragma unroll
            for (int i = 0; i < 5; i++) { s += sm.redP[t + i * 72]; s2 += sm.redQ[t + i * 72]; }
            float m = s * invS;
            float af = sm.a3v[t];
            float var = s2 * invS - m * m * af * (2.0f - af);
            float S = sm.g3v[t] * rsqrtf(var + EPSV);
            sm.redS[t] = S; sm.redC[t] = sm.be3v[t] - af * m * S;
        }
        __syncthreads();
        if (isNode) {
            const ull* Su = (const ull*)&sm.redS[half * 36];
            const ull* Cu = (const ull*)&sm.redC[half * 36];
            ull* hr = hU + n * RSU + half * 18;
            #pragma unroll
            for (int i = 0; i < 18; i++)
                hr[i] = fadd2(ffma2(accC[i], Su[i], Cu[i]), accR[i]);
        }
        __syncthreads();
    }

    // ---- striped max pool: 72 features x 5 stripes ----
    if (t < 360) {
        const int f = t % 72, sI = t / 72;
        float m = -INFINITY;
        const float* p = sm.h + f;
        for (int nn = sI; nn < SN; nn += 5) m = fmaxf(m, p[nn * RS]);
        sm.redP[t] = m;
    }
    __syncthreads();
    if (t < 72) {
        float m = sm.redP[t];
        #pragma unroll
        for (int i = 1; i < 5; i++) m = fmaxf(m, sm.redP[t + i * 72]);
        g_pooled[g * 72 + t] = m;
    }
}

// ---------------------------------------------------------------------------
// MLP: TM=16 rows/block, grid 128, 512 threads; split-k z2.
// ---------------------------------------------------------------------------
struct __align__(16) MSmem {
    ull rowsT[72][9];     // 8 row-pairs used + pad
    ull z1T[512][9];
    ull z2P[256][9];
    ull z2T[256][9];
};

__global__ void __launch_bounds__(512) mlp_kernel(
    const float* __restrict__ wf1, const float* __restrict__ bf1,
    const float* __restrict__ wf2, const float* __restrict__ bf2,
    const float* __restrict__ wm, const float* __restrict__ bm,
    const float* __restrict__ wl, const float* __restrict__ bl,
    float* __restrict__ out)
{
    extern __shared__ char smraw[];
    MSmem& sm = *reinterpret_cast<MSmem*>(smraw);
    const int tid = threadIdx.x;
    const int r0 = blockIdx.x * TM;

    {
        float* rf = (float*)sm.rowsT;
        for (int i = tid; i < TM * 72; i += 512) {
            const int k = i / TM, r = i % TM;
            rf[k * 18 + r] = g_pooled[(r0 + r) * 72 + k];
        }
    }
    __syncthreads();

    // z1 = relu(rows @ wf1 + bf1): 512 threads, 1 col each, 8 row-pair accs
    {
        const int j = tid;
        const float b = __ldg(bf1 + j);
        ull acc[8];
        #pragma unroll
        for (int i = 0; i < 8; i++) acc[i] = pk2(b, b);
        #pragma unroll 6
        for (int k = 0; k < 72; k++) {
            const float w = __ldg(wf1 + k * 512 + j);
            const ull ww = pk2(w, w);
            const ull* rw = sm.rowsT[k];
            #pragma unroll
            for (int i = 0; i < 8; i++) acc[i] = ffma2(ww, rw[i], acc[i]);
        }
        #pragma unroll
        for (int i = 0; i < 8; i++) {
            float2 v = upk2(acc[i]);
            sm.z1T[j][i] = pk2(fmaxf(v.x, 0.f), fmaxf(v.y, 0.f));
        }
    }
    __syncthreads();

    // z2 = relu(z1 @ wf2 + bf2): 256 cols x 2 k-halves
    {
        const int jj = tid & 255, half = tid >> 8;
        ull acc[8];
        if (half == 0) {
            const float b = __ldg(bf2 + jj);
            #pragma unroll
            for (int i = 0; i < 8; i++) acc[i] = pk2(b, b);
        } else {
            #pragma unroll
            for (int i = 0; i < 8; i++) acc[i] = 0ull;
        }
        const int k0 = half * 256;
        #pragma unroll 4
        for (int kk = 0; kk < 256; kk++) {
            const int k = k0 + kk;
            const float w = __ldg(wf2 + k * 256 + jj);
            const ull ww = pk2(w, w);
            const ull* zw = sm.z1T[k];
            #pragma unroll
            for (int i = 0; i < 8; i++) acc[i] = ffma2(ww, zw[i], acc[i]);
        }
        if (half == 1) {
            #pragma unroll
            for (int i = 0; i < 8; i++) sm.z2P[jj][i] = acc[i];
        }
        __syncthreads();
        if (half == 0) {
            #pragma unroll
            for (int i = 0; i < 8; i++) {
                float2 v = upk2(fadd2(acc[i], sm.z2P[jj][i]));
                sm.z2T[jj][i] = pk2(fmaxf(v.x, 0.f), fmaxf(v.y, 0.f));
            }
        }
        __syncthreads();
    }

    // heads: 16 warps, warp w handles row w
    {
        const int w = tid >> 5, lane = tid & 31;
        const int rp = w >> 1, hi = w & 1;
        float smv = 0.f, slv = 0.f;
        #pragma unroll 4
        for (int k = lane; k < 256; k += 32) {
            float2 v2 = upk2(sm.z2T[k][rp]);
            const float v = hi ? v2.y : v2.x;
            smv = fmaf(v, __ldg(wm + k), smv);
            slv = fmaf(v, __ldg(wl + k), slv);
        }
        #pragma unroll
        for (int o = 16; o > 0; o >>= 1) {
            smv += __shfl_xor_sync(0xffffffffu, smv, o);
            slv += __shfl_xor_sync(0xffffffffu, slv, o);
        }
        if (lane == 0) {
            out[r0 + w] = smv + __ldg(bm);
            const float ls = tanhf(slv + __ldg(bl));
            out[NG + r0 + w] = LSMIN + 0.5f * (LSMAX - LSMIN) * (ls + 1.0f);
        }
    }
}

// noop padding so ncu's fixed "-s 5" lands on gnn_kernel (5 mod 4 == 1)
__global__ void noop_kernel() {}

// ---------------------------------------------------------------------------
extern "C" void kernel_launch(void* const* d_in, const int* in_sizes, int n_in,
                              void* d_out, int out_size)
{
    const int*   x    = (const int*)d_in[0];
    const float* emb  = (const float*)d_in[2];
    const float* wc1  = (const float*)d_in[3];
    const float* bc1  = (const float*)d_in[4];
    const float* wc2  = (const float*)d_in[5];
    const float* bc2  = (const float*)d_in[6];
    const float* wc3  = (const float*)d_in[7];
    const float* bc3  = (const float*)d_in[8];
    const float* wr1  = (const float*)d_in[9];
    const float* br1  = (const float*)d_in[10];
    const float* wr2  = (const float*)d_in[11];
    const float* br2  = (const float*)d_in[12];
    const float* g1   = (const float*)d_in[13];
    const float* be1  = (const float*)d_in[14];
    const float* a1   = (const float*)d_in[15];
    const float* g2   = (const float*)d_in[16];
    const float* be2  = (const float*)d_in[17];
    const float* a2   = (const float*)d_in[18];
    const float* g3   = (const float*)d_in[19];
    const float* be3  = (const float*)d_in[20];
    const float* a3   = (const float*)d_in[21];
    const float* wf1  = (const float*)d_in[22];
    const float* bf1  = (const float*)d_in[23];
    const float* wf2  = (const float*)d_in[24];
    const float* bf2  = (const float*)d_in[25];
    const float* wm   = (const float*)d_in[26];
    const float* bm   = (const float*)d_in[27];
    const float* wl   = (const float*)d_in[28];
    const float* bl   = (const float*)d_in[29];
    float* out = (float*)d_out;

    cudaFuncSetAttribute(gnn_kernel, cudaFuncAttributeMaxDynamicSharedMemorySize,
                         (int)sizeof(Smem));
    cudaFuncSetAttribute(mlp_kernel, cudaFuncAttributeMaxDynamicSharedMemorySize,
                         (int)sizeof(MSmem));

    noop_kernel<<<1, 1>>>();

    gnn_kernel<<<NG, NT, sizeof(Smem)>>>(
        x, emb, wc1, bc1, wc2, bc2, wc3, bc3, wr1, br1, wr2, br2,
        g1, be1, a1, g2, be2, a2, g3, be3, a3);

    mlp_kernel<<<NG / TM, 512, sizeof(MSmem)>>>(
        wf1, bf1, wf2, bf2, wm, bm, wl, bl, out);

    noop_kernel<<<1, 1>>>();
}

// round 6
// speedup vs baseline: 1.1994x; 1.1994x over previous
#include <cuda_runtime.h>
#include <math.h>

#define NBOARD 13
#define SN 169
#define NG 2048
#define NT 192
#define EPSV 1e-5f
#define LSMIN -5.0f
#define LSMAX 2.0f
#define TM 16            // rows per MLP block

typedef unsigned long long ull;

__device__ __forceinline__ ull pk2(float x, float y) {
    ull r; asm("mov.b64 %0, {%1,%2};" : "=l"(r) : "f"(x), "f"(y)); return r;
}
__device__ __forceinline__ float2 upk2(ull a) {
    float2 v; asm("mov.b64 {%0,%1}, %2;" : "=f"(v.x), "=f"(v.y) : "l"(a)); return v;
}
__device__ __forceinline__ ull ffma2(ull a, ull b, ull c) {
    ull d; asm("fma.rn.f32x2 %0, %1, %2, %3;" : "=l"(d) : "l"(a), "l"(b), "l"(c)); return d;
}
__device__ __forceinline__ ull fadd2(ull a, ull b) {
    ull d; asm("add.rn.f32x2 %0, %1, %2;" : "=l"(d) : "l"(a), "l"(b)); return d;
}
__device__ __forceinline__ ull fmul2(ull a, ull b) {
    ull d; asm("mul.rn.f32x2 %0, %1, %2;" : "=l"(d) : "l"(a), "l"(b)); return d;
}

__device__ float g_pooled[NG * 72];

#define RS 74            // h row stride (floats); 37 ull
#define RSU 37

// No stage buffer: conv accumulators are staged in h itself for the stats
// pass (old h contents are dead once gathers are in registers).
// Total ~82KB -> 2 CTAs/SM.
struct __align__(16) Smem {
    float wc3[36 * 72];
    float wr2[36 * 72];
    float wc2[18 * 36];
    float wr1[18 * 36];
    float wc1p[18 * 20];
    float bc1[18], bc2[36], bc3[72];
    float br1[36], br2[72];
    float g1v[18], be1v[18], a1v[18];
    float g2v[36], be2v[36], a2v[36];
    float g3v[72], be3v[72], a3v[72];
    float embs[3 * 18];
    float redP[180], redQ[180];
    float redS[72], redC[72];
    float dis[170];
    float h[SN * RS];
};

__device__ __forceinline__ void cp_sm(float* dst, const float* src, int n, int t) {
    for (int i = t; i < n; i += NT) dst[i] = src[i];
}

// striped stats over h: Wf features x NS stripes (Wf*NS threads)
__device__ __forceinline__ void stats_striped(Smem& sm, int t, int Wf, int NS) {
    if (t < Wf * NS) {
        const int f = t % Wf, sI = t / Wf;
        float s = 0.f, s2 = 0.f;
        const float* p = sm.h + f;
        for (int n = sI; n < SN; n += NS) { float v = p[n * RS]; s += v; s2 = fmaf(v, v, s2); }
        sm.redP[t] = s; sm.redQ[t] = s2;
    }
}

__global__ void __launch_bounds__(NT, 2) gnn_kernel(
    const int* __restrict__ x,
    const float* __restrict__ emb,
    const float* __restrict__ wc1, const float* __restrict__ bc1,
    const float* __restrict__ wc2, const float* __restrict__ bc2,
    const float* __restrict__ wc3, const float* __restrict__ bc3,
    const float* __restrict__ wr1, const float* __restrict__ br1,
    const float* __restrict__ wr2, const float* __restrict__ br2,
    const float* __restrict__ g1, const float* __restrict__ be1, const float* __restrict__ a1,
    const float* __restrict__ g2, const float* __restrict__ be2, const float* __restrict__ a2,
    const float* __restrict__ g3, const float* __restrict__ be3, const float* __restrict__ a3)
{
    extern __shared__ char smraw[];
    Smem& sm = *reinterpret_cast<Smem*>(smraw);
    const int t = threadIdx.x;
    const int g = blockIdx.x;
    const bool isNode = (t < SN);
    ull* const hU = (ull*)sm.h;
    const float invS = 1.0f / (float)SN;

    cp_sm(sm.wc3, wc3, 36 * 72, t);
    cp_sm(sm.wr2, wr2, 36 * 72, t);
    cp_sm(sm.wc2, wc2, 18 * 36, t);
    cp_sm(sm.wr1, wr1, 18 * 36, t);
    for (int i = t; i < 18 * 20; i += NT) {
        const int k = i / 20, j = i % 20;
        sm.wc1p[i] = (j < 18) ? wc1[k * 18 + j] : 0.f;
    }
    cp_sm(sm.bc1, bc1, 18, t);  cp_sm(sm.bc2, bc2, 36, t);  cp_sm(sm.bc3, bc3, 72, t);
    cp_sm(sm.br1, br1, 36, t);  cp_sm(sm.br2, br2, 72, t);
    cp_sm(sm.g1v, g1, 18, t);   cp_sm(sm.be1v, be1, 18, t); cp_sm(sm.a1v, a1, 18, t);
    cp_sm(sm.g2v, g2, 36, t);   cp_sm(sm.be2v, be2, 36, t); cp_sm(sm.a2v, a2, 36, t);
    cp_sm(sm.g3v, g3, 72, t);   cp_sm(sm.be3v, be3, 72, t); cp_sm(sm.a3v, a3, 72, t);
    cp_sm(sm.embs, emb, 3 * 18, t);

    // ---- analytic hex topology ----
    int nbU[6];
    float dnb[6];
    float disn = 0.f;
    if (isNode) {
        const int r = t / NBOARD, c = t % NBOARD;
        const int drr[6] = { -1, 1, 0, 0, -1, 1 };
        const int dcc[6] = { 0, 0, -1, 1, 1, -1 };
        int deg = 1;
        #pragma unroll
        for (int j = 0; j < 6; j++) {
            int rr = r + drr[j], cc = c + dcc[j];
            if (rr >= 0 && rr < NBOARD && cc >= 0 && cc < NBOARD) {
                nbU[j] = (rr * NBOARD + cc) * RSU;
                deg++;
            } else {
                nbU[j] = t * RSU;
            }
        }
        disn = rsqrtf((float)deg);
        sm.dis[t] = disn;
    }
    __syncthreads();

    if (isNode) {
        const int xv = x[g * SN + t];
        #pragma unroll
        for (int k = 0; k < 18; k++) sm.h[t * RS + k] = sm.embs[xv * 18 + k];
        #pragma unroll
        for (int j = 0; j < 6; j++)
            dnb[j] = (nbU[j] == t * RSU) ? 0.f : sm.dis[nbU[j] / RSU];
    }
    __syncthreads();

    const ull dd = pk2(disn, disn);

    // ================= Layer 1 (18->18) + GN + identity residual ============
    {
        ull hkU[9], accC[9];
        if (isNode) {
            ull aU[9];
            const ull* hr = hU + t * RSU;
            #pragma unroll
            for (int i = 0; i < 9; i++) { hkU[i] = hr[i]; aU[i] = fmul2(hkU[i], dd); }
            #pragma unroll
            for (int j = 0; j < 6; j++) {
                const ull* p = hU + nbU[j];
                const ull wj = pk2(dnb[j], dnb[j]);
                #pragma unroll
                for (int i = 0; i < 9; i++) aU[i] = ffma2(wj, p[i], aU[i]);
            }
            #pragma unroll
            for (int i = 0; i < 9; i++) aU[i] = fmul2(aU[i], dd);
            const ull* bu = (const ull*)sm.bc1;
            #pragma unroll
            for (int i = 0; i < 9; i++) accC[i] = bu[i];
            #pragma unroll 2
            for (int kp = 0; kp < 9; kp++) {
                float2 av = upk2(aU[kp]);
                #pragma unroll
                for (int s = 0; s < 2; s++) {
                    const float ak = s ? av.y : av.x;
                    const ull aa = pk2(ak, ak);
                    const float* wrow = &sm.wc1p[(2 * kp + s) * 20];
                    const ulonglong2* w2 = (const ulonglong2*)wrow;
                    #pragma unroll
                    for (int jv = 0; jv < 4; jv++) {
                        ulonglong2 w = w2[jv];
                        accC[2 * jv]     = ffma2(aa, w.x, accC[2 * jv]);
                        accC[2 * jv + 1] = ffma2(aa, w.y, accC[2 * jv + 1]);
                    }
                    accC[8] = ffma2(aa, ((const ull*)wrow)[8], accC[8]);
                }
            }
        }
        __syncthreads();                 // gathers complete
        if (isNode) {
            ull* hr = hU + t * RSU;
            #pragma unroll
            for (int i = 0; i < 9; i++) hr[i] = accC[i];
        }
        __syncthreads();
        stats_striped(sm, t, 18, 10);
        __syncthreads();
        if (t < 18) {
            float s = 0.f, s2 = 0.f;
            #pragma unroll
            for (int i = 0; i < 10; i++) { s += sm.redP[t + i * 18]; s2 += sm.redQ[t + i * 18]; }
            float m = s * invS;
            float af = sm.a1v[t];
            float var = s2 * invS - m * m * af * (2.0f - af);
            float S = sm.g1v[t] * rsqrtf(var + EPSV);
            sm.redS[t] = S; sm.redC[t] = sm.be1v[t] - af * m * S;
        }
        __syncthreads();
        if (isNode) {
            const ull* Su = (const ull*)sm.redS;
            const ull* Cu = (const ull*)sm.redC;
            ull* hr = hU + t * RSU;
            #pragma unroll
            for (int i = 0; i < 9; i++)
                hr[i] = fadd2(ffma2(accC[i], Su[i], Cu[i]), hkU[i]);
        }
        __syncthreads();
    }

    // ====== Layer 2 (18->36): gather -> resid -> conv; stats in h ===========
    {
        ull accR[18], accC[18];
        if (isNode) {
            ull hkU[9], aU[9];
            const ull* hr = hU + t * RSU;
            #pragma unroll
            for (int i = 0; i < 9; i++) { hkU[i] = hr[i]; aU[i] = fmul2(hkU[i], dd); }
            #pragma unroll
            for (int j = 0; j < 6; j++) {
                const ull* p = hU + nbU[j];
                const ull wj = pk2(dnb[j], dnb[j]);
                #pragma unroll
                for (int i = 0; i < 9; i++) aU[i] = ffma2(wj, p[i], aU[i]);
            }
            #pragma unroll
            for (int i = 0; i < 9; i++) aU[i] = fmul2(aU[i], dd);

            const ull* buR = (const ull*)sm.br1;
            #pragma unroll
            for (int i = 0; i < 18; i++) accR[i] = buR[i];
            #pragma unroll 2
            for (int kp = 0; kp < 9; kp++) {
                float2 hv = upk2(hkU[kp]);
                #pragma unroll
                for (int s = 0; s < 2; s++) {
                    const float hk = s ? hv.y : hv.x;
                    const ull hh = pk2(hk, hk);
                    const ulonglong2* wr = (const ulonglong2*)&sm.wr1[(2 * kp + s) * 36];
                    #pragma unroll
                    for (int jv = 0; jv < 9; jv++) {
                        ulonglong2 u = wr[jv];
                        accR[2 * jv]     = ffma2(hh, u.x, accR[2 * jv]);
                        accR[2 * jv + 1] = ffma2(hh, u.y, accR[2 * jv + 1]);
                    }
                }
            }
            const ull* buC = (const ull*)sm.bc2;
            #pragma unroll
            for (int i = 0; i < 18; i++) accC[i] = buC[i];
            #pragma unroll 2
            for (int kp = 0; kp < 9; kp++) {
                float2 av = upk2(aU[kp]);
                #pragma unroll
                for (int s = 0; s < 2; s++) {
                    const float ak = s ? av.y : av.x;
                    const ull aa = pk2(ak, ak);
                    const ulonglong2* wc = (const ulonglong2*)&sm.wc2[(2 * kp + s) * 36];
                    #pragma unroll
                    for (int jv = 0; jv < 9; jv++) {
                        ulonglong2 w = wc[jv];
                        accC[2 * jv]     = ffma2(aa, w.x, accC[2 * jv]);
                        accC[2 * jv + 1] = ffma2(aa, w.y, accC[2 * jv + 1]);
                    }
                }
            }
        }
        __syncthreads();
        if (isNode) {
            ull* hr = hU + t * RSU;
            #pragma unroll
            for (int i = 0; i < 18; i++) hr[i] = accC[i];
        }
        __syncthreads();
        stats_striped(sm, t, 36, 5);
        __syncthreads();
        if (t < 36) {
            float s = 0.f, s2 = 0.f;
            #pragma unroll
            for (int i = 0; i < 5; i++) { s += sm.redP[t + i * 36]; s2 += sm.redQ[t + i * 36]; }
            float m = s * invS;
            float af = sm.a2v[t];
            float var = s2 * invS - m * m * af * (2.0f - af);
            float S = sm.g2v[t] * rsqrtf(var + EPSV);
            sm.redS[t] = S; sm.redC[t] = sm.be2v[t] - af * m * S;
        }
        __syncthreads();
        if (isNode) {
            const ull* Su = (const ull*)sm.redS;
            const ull* Cu = (const ull*)sm.redC;
            ull* hr = hU + t * RSU;
            #pragma unroll
            for (int i = 0; i < 18; i++)
                hr[i] = fadd2(ffma2(accC[i], Su[i], Cu[i]), accR[i]);
        }
        __syncthreads();
    }

    // ====== Layer 3 (36->72): gather -> resid -> conv; stats in h ==========
    {
        ull accR[36], accC[36];
        {
            ull aU[18];
            if (isNode) {
                ull hkU[18];
                const ull* hr = hU + t * RSU;
                #pragma unroll
                for (int i = 0; i < 18; i++) { hkU[i] = hr[i]; aU[i] = fmul2(hkU[i], dd); }
                #pragma unroll
                for (int j = 0; j < 6; j++) {
                    const ull* p = hU + nbU[j];
                    const ull wj = pk2(dnb[j], dnb[j]);
                    #pragma unroll
                    for (int i = 0; i < 18; i++) aU[i] = ffma2(wj, p[i], aU[i]);
                }
                #pragma unroll
                for (int i = 0; i < 18; i++) aU[i] = fmul2(aU[i], dd);

                // residual proj (consumes hkU)
                const ull* buR = (const ull*)sm.br2;
                #pragma unroll
                for (int i = 0; i < 36; i++) accR[i] = buR[i];
                #pragma unroll 1
                for (int kp = 0; kp < 18; kp++) {
                    float2 hv = upk2(hkU[kp]);
                    #pragma unroll
                    for (int s = 0; s < 2; s++) {
                        const float hk = s ? hv.y : hv.x;
                        const ull hh = pk2(hk, hk);
                        const ulonglong2* wr = (const ulonglong2*)&sm.wr2[(2 * kp + s) * 72];
                        #pragma unroll
                        for (int jv = 0; jv < 18; jv++) {
                            ulonglong2 u = wr[jv];
                            accR[2 * jv]     = ffma2(hh, u.x, accR[2 * jv]);
                            accR[2 * jv + 1] = ffma2(hh, u.y, accR[2 * jv + 1]);
                        }
                    }
                }
                // conv (consumes aU)
                const ull* buC = (const ull*)sm.bc3;
                #pragma unroll
                for (int i = 0; i < 36; i++) accC[i] = buC[i];
                #pragma unroll 1
                for (int kp = 0; kp < 18; kp++) {
                    float2 av = upk2(aU[kp]);
                    #pragma unroll
                    for (int s = 0; s < 2; s++) {
                        const float ak = s ? av.y : av.x;
                        const ull aa = pk2(ak, ak);
                        const ulonglong2* wc = (const ulonglong2*)&sm.wc3[(2 * kp + s) * 72];
                        #pragma unroll
                        for (int jv = 0; jv < 18; jv++) {
                            ulonglong2 w = wc[jv];
                            accC[2 * jv]     = ffma2(aa, w.x, accC[2 * jv]);
                            accC[2 * jv + 1] = ffma2(aa, w.y, accC[2 * jv + 1]);
                        }
                    }
                }
            }
        }
        __syncthreads();
        if (isNode) {
            ull* hr = hU + t * RSU;
            #pragma unroll
            for (int i = 0; i < 36; i++) hr[i] = accC[i];
        }
        __syncthreads();
        stats_striped(sm, t, 72, 2);
        __syncthreads();
        if (t < 72) {
            float s = sm.redP[t] + sm.redP[t + 72];
            float s2 = sm.redQ[t] + sm.redQ[t + 72];
            float m = s * invS;
            float af = sm.a3v[t];
            float var = s2 * invS - m * m * af * (2.0f - af);
            float S = sm.g3v[t] * rsqrtf(var + EPSV);
            sm.redS[t] = S; sm.redC[t] = sm.be3v[t] - af * m * S;
        }
        __syncthreads();
        if (isNode) {
            const ull* Su = (const ull*)sm.redS;
            const ull* Cu = (const ull*)sm.redC;
            ull* hr = hU + t * RSU;
            #pragma unroll
            for (int i = 0; i < 36; i++)
                hr[i] = fadd2(ffma2(accC[i], Su[i], Cu[i]), accR[i]);
        }
        __syncthreads();
    }

    // ---- striped max pool: 72 features x 2 stripes ----
    if (t < 144) {
        const int f = t % 72, sI = t / 72;
        float m = -INFINITY;
        const float* p = sm.h + f;
        for (int n = sI; n < SN; n += 2) m = fmaxf(m, p[n * RS]);
        sm.redP[t] = m;
    }
    __syncthreads();
    if (t < 72) g_pooled[g * 72 + t] = fmaxf(sm.redP[t], sm.redP[t + 72]);
}

// ---------------------------------------------------------------------------
// MLP: TM=16 rows/block, grid 128, 512 threads; split-k z2.
// ---------------------------------------------------------------------------
struct __align__(16) MSmem {
    ull rowsT[72][9];
    ull z1T[512][9];
    ull z2P[256][9];
    ull z2T[256][9];
};

__global__ void __launch_bounds__(512) mlp_kernel(
    const float* __restrict__ wf1, const float* __restrict__ bf1,
    const float* __restrict__ wf2, const float* __restrict__ bf2,
    const float* __restrict__ wm, const float* __restrict__ bm,
    const float* __restrict__ wl, const float* __restrict__ bl,
    float* __restrict__ out)
{
    extern __shared__ char smraw[];
    MSmem& sm = *reinterpret_cast<MSmem*>(smraw);
    const int tid = threadIdx.x;
    const int r0 = blockIdx.x * TM;

    {
        float* rf = (float*)sm.rowsT;
        for (int i = tid; i < TM * 72; i += 512) {
            const int k = i / TM, r = i % TM;
            rf[k * 18 + r] = g_pooled[(r0 + r) * 72 + k];
        }
    }
    __syncthreads();

    {
        const int j = tid;
        const float b = __ldg(bf1 + j);
        ull acc[8];
        #pragma unroll
        for (int i = 0; i < 8; i++) acc[i] = pk2(b, b);
        #pragma unroll 6
        for (int k = 0; k < 72; k++) {
            const float w = __ldg(wf1 + k * 512 + j);
            const ull ww = pk2(w, w);
            const ull* rw = sm.rowsT[k];
            #pragma unroll
            for (int i = 0; i < 8; i++) acc[i] = ffma2(ww, rw[i], acc[i]);
        }
        #pragma unroll
        for (int i = 0; i < 8; i++) {
            float2 v = upk2(acc[i]);
            sm.z1T[j][i] = pk2(fmaxf(v.x, 0.f), fmaxf(v.y, 0.f));
        }
    }
    __syncthreads();

    {
        const int jj = tid & 255, half = tid >> 8;
        ull acc[8];
        if (half == 0) {
            const float b = __ldg(bf2 + jj);
            #pragma unroll
            for (int i = 0; i < 8; i++) acc[i] = pk2(b, b);
        } else {
            #pragma unroll
            for (int i = 0; i < 8; i++) acc[i] = 0ull;
        }
        const int k0 = half * 256;
        #pragma unroll 4
        for (int kk = 0; kk < 256; kk++) {
            const int k = k0 + kk;
            const float w = __ldg(wf2 + k * 256 + jj);
            const ull ww = pk2(w, w);
            const ull* zw = sm.z1T[k];
            #pragma unroll
            for (int i = 0; i < 8; i++) acc[i] = ffma2(ww, zw[i], acc[i]);
        }
        if (half == 1) {
            #pragma unroll
            for (int i = 0; i < 8; i++) sm.z2P[jj][i] = acc[i];
        }
        __syncthreads();
        if (half == 0) {
            #pragma unroll
            for (int i = 0; i < 8; i++) {
                float2 v = upk2(fadd2(acc[i], sm.z2P[jj][i]));
                sm.z2T[jj][i] = pk2(fmaxf(v.x, 0.f), fmaxf(v.y, 0.f));
            }
        }
        __syncthreads();
    }

    {
        const int w = tid >> 5, lane = tid & 31;
        const int rp = w >> 1, hi = w & 1;
        float smv = 0.f, slv = 0.f;
        #pragma unroll 4
        for (int k = lane; k < 256; k += 32) {
            float2 v2 = upk2(sm.z2T[k][rp]);
            const float v = hi ? v2.y : v2.x;
            smv = fmaf(v, __ldg(wm + k), smv);
            slv = fmaf(v, __ldg(wl + k), slv);
        }
        #pragma unroll
        for (int o = 16; o > 0; o >>= 1) {
            smv += __shfl_xor_sync(0xffffffffu, smv, o);
            slv += __shfl_xor_sync(0xffffffffu, slv, o);
        }
        if (lane == 0) {
            out[r0 + w] = smv + __ldg(bm);
            const float ls = tanhf(slv + __ldg(bl));
            out[NG + r0 + w] = LSMIN + 0.5f * (LSMAX - LSMIN) * (ls + 1.0f);
        }
    }
}

// ---------------------------------------------------------------------------
extern "C" void kernel_launch(void* const* d_in, const int* in_sizes, int n_in,
                              void* d_out, int out_size)
{
    const int*   x    = (const int*)d_in[0];
    const float* emb  = (const float*)d_in[2];
    const float* wc1  = (const float*)d_in[3];
    const float* bc1  = (const float*)d_in[4];
    const float* wc2  = (const float*)d_in[5];
    const float* bc2  = (const float*)d_in[6];
    const float* wc3  = (const float*)d_in[7];
    const float* bc3  = (const float*)d_in[8];
    const float* wr1  = (const float*)d_in[9];
    const float* br1  = (const float*)d_in[10];
    const float* wr2  = (const float*)d_in[11];
    const float* br2  = (const float*)d_in[12];
    const float* g1   = (const float*)d_in[13];
    const float* be1  = (const float*)d_in[14];
    const float* a1   = (const float*)d_in[15];
    const float* g2   = (const float*)d_in[16];
    const float* be2  = (const float*)d_in[17];
    const float* a2   = (const float*)d_in[18];
    const float* g3   = (const float*)d_in[19];
    const float* be3  = (const float*)d_in[20];
    const float* a3   = (const float*)d_in[21];
    const float* wf1  = (const float*)d_in[22];
    const float* bf1  = (const float*)d_in[23];
    const float* wf2  = (const float*)d_in[24];
    const float* bf2  = (const float*)d_in[25];
    const float* wm   = (const float*)d_in[26];
    const float* bm   = (const float*)d_in[27];
    const float* wl   = (const float*)d_in[28];
    const float* bl   = (const float*)d_in[29];
    float* out = (float*)d_out;

    cudaFuncSetAttribute(gnn_kernel, cudaFuncAttributeMaxDynamicSharedMemorySize,
                         (int)sizeof(Smem));
    cudaFuncSetAttribute(mlp_kernel, cudaFuncAttributeMaxDynamicSharedMemorySize,
                         (int)sizeof(MSmem));

    gnn_kernel<<<NG, NT, sizeof(Smem)>>>(
        x, emb, wc1, bc1, wc2, bc2, wc3, bc3, wr1, br1, wr2, br2,
        g1, be1, a1, g2, be2, a2, g3, be3, a3);

    mlp_kernel<<<NG / TM, 512, sizeof(MSmem)>>>(
        wf1, bf1, wf2, bf2, wm, bm, wl, bl, out);
}

// round 8
// speedup vs baseline: 1.3159x; 1.0971x over previous
#include <cuda_runtime.h>
#include <math.h>

#define NBOARD 13
#define SN 169
#define NG 2048
#define NT 192
#define GRID 148         // persistent: one CTA per SM, each loops over graphs
#define EPSV 1e-5f
#define LSMIN -5.0f
#define LSMAX 2.0f

typedef unsigned long long ull;

__device__ __forceinline__ ull pk2(float x, float y) {
    ull r; asm("mov.b64 %0, {%1,%2};" : "=l"(r) : "f"(x), "f"(y)); return r;
}
__device__ __forceinline__ float2 upk2(ull a) {
    float2 v; asm("mov.b64 {%0,%1}, %2;" : "=f"(v.x), "=f"(v.y) : "l"(a)); return v;
}
__device__ __forceinline__ ull ffma2(ull a, ull b, ull c) {
    ull d; asm("fma.rn.f32x2 %0, %1, %2, %3;" : "=l"(d) : "l"(a), "l"(b), "l"(c)); return d;
}
__device__ __forceinline__ ull fadd2(ull a, ull b) {
    ull d; asm("add.rn.f32x2 %0, %1, %2;" : "=l"(d) : "l"(a), "l"(b)); return d;
}

__device__ float g_pooled[NG * 72];

// R2 layout: h stride 73 (scalar gathers, conflict-free), t1 stride 74 (ull).
struct __align__(16) Smem {
    float wc3[36 * 72];
    float wr2[36 * 72];
    float wc2[18 * 36];
    float wr1[18 * 36];
    float wc1[18 * 18];
    float bc1[18], bc2[36], bc3[72];
    float br1[36], br2[72];
    float g1v[18], be1v[18], a1v[18];
    float g2v[36], be2v[36], a2v[36];
    float g3v[72], be3v[72], a3v[72];
    float embs[3 * 18];
    float redP[180], redQ[180];
    float redS[72], redC[72];
    float dis[170];
    float t1[SN * 74];
    float h[SN * 73];
};

__device__ __forceinline__ void cp_sm(float* dst, const float* src, int n, int t) {
    for (int i = t; i < n; i += NT) dst[i] = src[i];
}

// striped stats over t1: Wf features x NS stripes
__device__ __forceinline__ void stats_striped(Smem& sm, int t, int Wf, int NS) {
    if (t < Wf * NS) {
        const int f = t % Wf, sI = t / Wf;
        float s = 0.f, s2 = 0.f;
        const float* p = sm.t1 + f;
        for (int n = sI; n < SN; n += NS) { float v = p[n * 74]; s += v; s2 = fmaf(v, v, s2); }
        sm.redP[t] = s; sm.redQ[t] = s2;
    }
}

__global__ void __launch_bounds__(NT) gnn_kernel(
    const int* __restrict__ x,
    const float* __restrict__ emb,
    const float* __restrict__ wc1, const float* __restrict__ bc1,
    const float* __restrict__ wc2, const float* __restrict__ bc2,
    const float* __restrict__ wc3, const float* __restrict__ bc3,
    const float* __restrict__ wr1, const float* __restrict__ br1,
    const float* __restrict__ wr2, const float* __restrict__ br2,
    const float* __restrict__ g1, const float* __restrict__ be1, const float* __restrict__ a1,
    const float* __restrict__ g2, const float* __restrict__ be2, const float* __restrict__ a2,
    const float* __restrict__ g3, const float* __restrict__ be3, const float* __restrict__ a3)
{
    extern __shared__ char smraw[];
    Smem& sm = *reinterpret_cast<Smem*>(smraw);
    const int t = threadIdx.x;
    const bool isNode = (t < SN);
    ull* const t1U = (ull*)sm.t1;
    const float* hb = sm.h;
    const float invS = 1.0f / (float)SN;

    // ---- stage weights/params ONCE per CTA (persistent) ----
    cp_sm(sm.wc3, wc3, 36 * 72, t);
    cp_sm(sm.wr2, wr2, 36 * 72, t);
    cp_sm(sm.wc2, wc2, 18 * 36, t);
    cp_sm(sm.wr1, wr1, 18 * 36, t);
    cp_sm(sm.wc1, wc1, 18 * 18, t);
    cp_sm(sm.bc1, bc1, 18, t);  cp_sm(sm.bc2, bc2, 36, t);  cp_sm(sm.bc3, bc3, 72, t);
    cp_sm(sm.br1, br1, 36, t);  cp_sm(sm.br2, br2, 72, t);
    cp_sm(sm.g1v, g1, 18, t);   cp_sm(sm.be1v, be1, 18, t); cp_sm(sm.a1v, a1, 18, t);
    cp_sm(sm.g2v, g2, 36, t);   cp_sm(sm.be2v, be2, 36, t); cp_sm(sm.a2v, a2, 36, t);
    cp_sm(sm.g3v, g3, 72, t);   cp_sm(sm.be3v, be3, 72, t); cp_sm(sm.a3v, a3, 72, t);
    cp_sm(sm.embs, emb, 3 * 18, t);

    // ---- analytic hex topology ONCE ----
    int nbo[6];
    int nbi[6];
    float dnb[6];
    float disn = 0.f;
    if (isNode) {
        const int r = t / NBOARD, c = t % NBOARD;
        const int drr[6] = { -1, 1, 0, 0, -1, 1 };
        const int dcc[6] = { 0, 0, -1, 1, 1, -1 };
        int deg = 1;
        #pragma unroll
        for (int j = 0; j < 6; j++) {
            int rr = r + drr[j], cc = c + dcc[j];
            if (rr >= 0 && rr < NBOARD && cc >= 0 && cc < NBOARD) {
                nbi[j] = rr * NBOARD + cc;
                deg++;
            } else {
                nbi[j] = t;
            }
            nbo[j] = nbi[j] * 73;
        }
        disn = rsqrtf((float)deg);
        sm.dis[t] = disn;
    }
    __syncthreads();          // block-wide: all dis[] written before any read
    if (isNode) {
        #pragma unroll
        for (int j = 0; j < 6; j++)
            dnb[j] = (nbi[j] == t) ? 0.f : sm.dis[nbi[j]];
    }
    __syncthreads();

    // =================== persistent loop over graphs ========================
    for (int g = blockIdx.x; g < NG; g += GRID) {

        // ---- embedding lookup ----
        if (isNode) {
            const int xv = x[g * SN + t];
            #pragma unroll
            for (int k = 0; k < 18; k++) sm.h[t * 73 + k] = sm.embs[xv * 18 + k];
        }
        __syncthreads();

        // ============== Layer 1: SGConv(18->18) + GN + identity residual ====
        {
            ull acc2[9];
            if (isNode) {
                const ull* bu = (const ull*)sm.bc1;
                #pragma unroll
                for (int j = 0; j < 9; j++) acc2[j] = bu[j];
                #pragma unroll 2
                for (int k = 0; k < 18; k++) {
                    float a = sm.h[t * 73 + k] * disn;
                    #pragma unroll
                    for (int j = 0; j < 6; j++) a += hb[nbo[j] + k] * dnb[j];
                    a *= disn;
                    const ull aa = pk2(a, a);
                    const ull* w = (const ull*)&sm.wc1[k * 18];
                    #pragma unroll
                    for (int j = 0; j < 9; j++) acc2[j] = ffma2(aa, w[j], acc2[j]);
                }
                ull* st = t1U + t * 37;
                #pragma unroll
                for (int j = 0; j < 9; j++) st[j] = acc2[j];
            }
            __syncthreads();
            stats_striped(sm, t, 18, 10);
            __syncthreads();
            if (t < 18) {
                float s = 0.f, s2 = 0.f;
                #pragma unroll
                for (int i = 0; i < 10; i++) { s += sm.redP[t + i * 18]; s2 += sm.redQ[t + i * 18]; }
                float m = s * invS;
                float af = sm.a1v[t];
                float var = s2 * invS - m * m * af * (2.0f - af);
                float S = sm.g1v[t] * rsqrtf(var + EPSV);
                sm.redS[t] = S; sm.redC[t] = sm.be1v[t] - af * m * S;
            }
            __syncthreads();
            if (isNode) {
                const ull* st = t1U + t * 37;
                const ull* Su = (const ull*)sm.redS;
                const ull* Cu = (const ull*)sm.redC;
                #pragma unroll
                for (int j = 0; j < 9; j++) {
                    float2 v = upk2(ffma2(st[j], Su[j], Cu[j]));
                    sm.h[t * 73 + 2 * j]     += v.x;
                    sm.h[t * 73 + 2 * j + 1] += v.y;
                }
            }
            __syncthreads();
        }

        // ===== Layer 2: SGConv(18->36) + GN + resid proj, one k-loop ========
        {
            ull accC[18], accR[18];
            if (isNode) {
                const ull* buC = (const ull*)sm.bc2;
                const ull* buR = (const ull*)sm.br1;
                #pragma unroll
                for (int i = 0; i < 18; i++) { accC[i] = buC[i]; accR[i] = buR[i]; }
                #pragma unroll 2
                for (int k = 0; k < 18; k++) {
                    const float hk = sm.h[t * 73 + k];
                    float a = hk * disn;
                    #pragma unroll
                    for (int j = 0; j < 6; j++) a += hb[nbo[j] + k] * dnb[j];
                    a *= disn;
                    const ull aa = pk2(a, a);
                    const ull hh = pk2(hk, hk);
                    const ulonglong2* wc = (const ulonglong2*)&sm.wc2[k * 36];
                    const ulonglong2* wr = (const ulonglong2*)&sm.wr1[k * 36];
                    #pragma unroll
                    for (int jv = 0; jv < 9; jv++) {
                        ulonglong2 w = wc[jv];
                        accC[2 * jv]     = ffma2(aa, w.x, accC[2 * jv]);
                        accC[2 * jv + 1] = ffma2(aa, w.y, accC[2 * jv + 1]);
                        ulonglong2 u = wr[jv];
                        accR[2 * jv]     = ffma2(hh, u.x, accR[2 * jv]);
                        accR[2 * jv + 1] = ffma2(hh, u.y, accR[2 * jv + 1]);
                    }
                }
                ull* st = t1U + t * 37;
                #pragma unroll
                for (int i = 0; i < 18; i++) st[i] = accC[i];
            }
            __syncthreads();
            stats_striped(sm, t, 36, 5);
            __syncthreads();
            if (t < 36) {
                float s = 0.f, s2 = 0.f;
                #pragma unroll
                for (int i = 0; i < 5; i++) { s += sm.redP[t + i * 36]; s2 += sm.redQ[t + i * 36]; }
                float m = s * invS;
                float af = sm.a2v[t];
                float var = s2 * invS - m * m * af * (2.0f - af);
                float S = sm.g2v[t] * rsqrtf(var + EPSV);
                sm.redS[t] = S; sm.redC[t] = sm.be2v[t] - af * m * S;
            }
            __syncthreads();
            if (isNode) {
                const ull* st = t1U + t * 37;
                const ull* Su = (const ull*)sm.redS;
                const ull* Cu = (const ull*)sm.redC;
                #pragma unroll
                for (int j = 0; j < 18; j++) {
                    float2 v = upk2(fadd2(ffma2(st[j], Su[j], Cu[j]), accR[j]));
                    sm.h[t * 73 + 2 * j]     = v.x;
                    sm.h[t * 73 + 2 * j + 1] = v.y;
                }
            }
            __syncthreads();
        }

        // ===== Layer 3: resid proj then conv (R2 structure) =================
        {
            ull accR[36];
            if (isNode) {
                const ull* buR = (const ull*)sm.br2;
                #pragma unroll
                for (int j = 0; j < 36; j++) accR[j] = buR[j];
                #pragma unroll 1
                for (int k = 0; k < 36; k++) {
                    const float hk = sm.h[t * 73 + k];
                    const ull hh = pk2(hk, hk);
                    const ulonglong2* wr = (const ulonglong2*)&sm.wr2[k * 72];
                    #pragma unroll
                    for (int jv = 0; jv < 18; jv++) {
                        ulonglong2 u = wr[jv];
                        accR[2 * jv]     = ffma2(hh, u.x, accR[2 * jv]);
                        accR[2 * jv + 1] = ffma2(hh, u.y, accR[2 * jv + 1]);
                    }
                }
            }
            {
                ull accC[36];
                if (isNode) {
                    const ull* buC = (const ull*)sm.bc3;
                    #pragma unroll
                    for (int j = 0; j < 36; j++) accC[j] = buC[j];
                    #pragma unroll 1
                    for (int k = 0; k < 36; k++) {
                        float a = sm.h[t * 73 + k] * disn;
                        #pragma unroll
                        for (int j = 0; j < 6; j++) a += hb[nbo[j] + k] * dnb[j];
                        a *= disn;
                        const ull aa = pk2(a, a);
                        const ulonglong2* wc = (const ulonglong2*)&sm.wc3[k * 72];
                        #pragma unroll
                        for (int jv = 0; jv < 18; jv++) {
                            ulonglong2 w = wc[jv];
                            accC[2 * jv]     = ffma2(aa, w.x, accC[2 * jv]);
                            accC[2 * jv + 1] = ffma2(aa, w.y, accC[2 * jv + 1]);
                        }
                    }
                    ull* st = t1U + t * 37;
                    #pragma unroll
                    for (int j = 0; j < 36; j++) st[j] = accC[j];
                }
            }
            __syncthreads();
            stats_striped(sm, t, 72, 2);
            __syncthreads();
            if (t < 72) {
                float s = sm.redP[t] + sm.redP[t + 72];
                float s2 = sm.redQ[t] + sm.redQ[t + 72];
                float m = s * invS;
                float af = sm.a3v[t];
                float var = s2 * invS - m * m * af * (2.0f - af);
                float S = sm.g3v[t] * rsqrtf(var + EPSV);
                sm.redS[t] = S; sm.redC[t] = sm.be3v[t] - af * m * S;
            }
            __syncthreads();
            if (isNode) {
                const ull* st = t1U + t * 37;
                const ull* Su = (const ull*)sm.redS;
                const ull* Cu = (const ull*)sm.redC;
                #pragma unroll
                for (int j = 0; j < 36; j++) {
                    float2 v = upk2(fadd2(ffma2(st[j], Su[j], Cu[j]), accR[j]));
                    sm.h[t * 73 + 2 * j]     = v.x;
                    sm.h[t * 73 + 2 * j + 1] = v.y;
                }
            }
            __syncthreads();
        }

        // ---- striped max pool: 72 features x 2 stripes ----
        if (t < 144) {
            const int f = t % 72, sI = t / 72;
            float m = -INFINITY;
            const float* p = sm.h + f;
            for (int n = sI; n < SN; n += 2) m = fmaxf(m, p[n * 73]);
            sm.redP[t] = m;
        }
        __syncthreads();
        if (t < 72) g_pooled[g * 72 + t] = fmaxf(sm.redP[t], sm.redP[t + 72]);
        __syncthreads();   // redP reuse + h overwrite next iteration
    }
}

// ---------------------------------------------------------------------------
// MLP (R3/R5 exact, 35.7us): TM=8, grid 256, 512 threads, split-k z2.
// ---------------------------------------------------------------------------
struct __align__(16) MSmem {
    ull rowsT[72][5];
    ull z1T[512][5];
    ull z2P[256][5];
    ull z2T[256][5];
};

__global__ void __launch_bounds__(512, 2) mlp_kernel(
    const float* __restrict__ wf1, const float* __restrict__ bf1,
    const float* __restrict__ wf2, const float* __restrict__ bf2,
    const float* __restrict__ wm, const float* __restrict__ bm,
    const float* __restrict__ wl, const float* __restrict__ bl,
    float* __restrict__ out)
{
    extern __shared__ char smraw[];
    MSmem& sm = *reinterpret_cast<MSmem*>(smraw);
    const int tid = threadIdx.x;
    const int r0 = blockIdx.x * 8;

    {
        float* rf = (float*)sm.rowsT;
        for (int i = tid; i < 8 * 72; i += 512) {
            const int k = i / 8, r = i % 8;
            rf[k * 10 + r] = g_pooled[(r0 + r) * 72 + k];
        }
    }
    __syncthreads();

    {
        const int j = tid;
        const float b = __ldg(bf1 + j);
        ull acc[4];
        #pragma unroll
        for (int i = 0; i < 4; i++) acc[i] = pk2(b, b);
        #pragma unroll 8
        for (int k = 0; k < 72; k++) {
            const float w = __ldg(wf1 + k * 512 + j);
            const ull ww = pk2(w, w);
            const ull* rw = sm.rowsT[k];
            #pragma unroll
            for (int i = 0; i < 4; i++) acc[i] = ffma2(ww, rw[i], acc[i]);
        }
        #pragma unroll
        for (int i = 0; i < 4; i++) {
            float2 v = upk2(acc[i]);
            sm.z1T[j][i] = pk2(fmaxf(v.x, 0.f), fmaxf(v.y, 0.f));
        }
    }
    __syncthreads();

    {
        const int jj = tid & 255, half = tid >> 8;
        ull acc[4];
        if (half == 0) {
            const float b = __ldg(bf2 + jj);
            #pragma unroll
            for (int i = 0; i < 4; i++) acc[i] = pk2(b, b);
        } else {
            #pragma unroll
            for (int i = 0; i < 4; i++) acc[i] = 0ull;
        }
        const int k0 = half * 256;
        #pragma unroll 8
        for (int kk = 0; kk < 256; kk++) {
            const int k = k0 + kk;
            const float w = __ldg(wf2 + k * 256 + jj);
            const ull ww = pk2(w, w);
            const ull* zw = sm.z1T[k];
            #pragma unroll
            for (int i = 0; i < 4; i++) acc[i] = ffma2(ww, zw[i], acc[i]);
        }
        if (half == 1) {
            #pragma unroll
            for (int i = 0; i < 4; i++) sm.z2P[jj][i] = acc[i];
        }
        __syncthreads();
        if (half == 0) {
            #pragma unroll
            for (int i = 0; i < 4; i++) {
                float2 v = upk2(fadd2(acc[i], sm.z2P[jj][i]));
                sm.z2T[jj][i] = pk2(fmaxf(v.x, 0.f), fmaxf(v.y, 0.f));
            }
        }
        __syncthreads();
    }

    {
        const int w = tid >> 5, lane = tid & 31;
        if (w < 8) {
            const int rp = w >> 1, hi = w & 1;
            float smv = 0.f, slv = 0.f;
            #pragma unroll 4
            for (int k = lane; k < 256; k += 32) {
                float2 v2 = upk2(sm.z2T[k][rp]);
                const float v = hi ? v2.y : v2.x;
                smv = fmaf(v, __ldg(wm + k), smv);
                slv = fmaf(v, __ldg(wl + k), slv);
            }
            #pragma unroll
            for (int o = 16; o > 0; o >>= 1) {
                smv += __shfl_xor_sync(0xffffffffu, smv, o);
                slv += __shfl_xor_sync(0xffffffffu, slv, o);
            }
            if (lane == 0) {
                out[r0 + w] = smv + __ldg(bm);
                const float ls = tanhf(slv + __ldg(bl));
                out[NG + r0 + w] = LSMIN + 0.5f * (LSMAX - LSMIN) * (ls + 1.0f);
            }
        }
    }
}

// ---------------------------------------------------------------------------
extern "C" void kernel_launch(void* const* d_in, const int* in_sizes, int n_in,
                              void* d_out, int out_size)
{
    const int*   x    = (const int*)d_in[0];
    const float* emb  = (const float*)d_in[2];
    const float* wc1  = (const float*)d_in[3];
    const float* bc1  = (const float*)d_in[4];
    const float* wc2  = (const float*)d_in[5];
    const float* bc2  = (const float*)d_in[6];
    const float* wc3  = (const float*)d_in[7];
    const float* bc3  = (const float*)d_in[8];
    const float* wr1  = (const float*)d_in[9];
    const float* br1  = (const float*)d_in[10];
    const float* wr2  = (const float*)d_in[11];
    const float* br2  = (const float*)d_in[12];
    const float* g1   = (const float*)d_in[13];
    const float* be1  = (const float*)d_in[14];
    const float* a1   = (const float*)d_in[15];
    const float* g2   = (const float*)d_in[16];
    const float* be2  = (const float*)d_in[17];
    const float* a2   = (const float*)d_in[18];
    const float* g3   = (const float*)d_in[19];
    const float* be3  = (const float*)d_in[20];
    const float* a3   = (const float*)d_in[21];
    const float* wf1  = (const float*)d_in[22];
    const float* bf1  = (const float*)d_in[23];
    const float* wf2  = (const float*)d_in[24];
    const float* bf2  = (const float*)d_in[25];
    const float* wm   = (const float*)d_in[26];
    const float* bm   = (const float*)d_in[27];
    const float* wl   = (const float*)d_in[28];
    const float* bl   = (const float*)d_in[29];
    float* out = (float*)d_out;

    cudaFuncSetAttribute(gnn_kernel, cudaFuncAttributeMaxDynamicSharedMemorySize,
                         (int)sizeof(Smem));
    cudaFuncSetAttribute(mlp_kernel, cudaFuncAttributeMaxDynamicSharedMemorySize,
                         (int)sizeof(MSmem));

    gnn_kernel<<<GRID, NT, sizeof(Smem)>>>(
        x, emb, wc1, bc1, wc2, bc2, wc3, bc3, wr1, br1, wr2, br2,
        g1, be1, a1, g2, be2, a2, g3, be3, a3);

    mlp_kernel<<<NG / 8, 512, sizeof(MSmem)>>>(
        wf1, bf1, wf2, bf2, wm, bm, wl, bl, out);
}

// round 9
// speedup vs baseline: 1.4081x; 1.0701x over previous
#include <cuda_runtime.h>
#include <math.h>

#define NBOARD 13
#define SN 169
#define NG 2048
#define NT 192
#define GRID 148
#define EPSV 1e-5f
#define LSMIN -5.0f
#define LSMAX 2.0f

#define HSF 78            // h row stride (floats): FEAT [0,36), AGG [40,76)
#define AOFF 40
#define OSF 38            // out row stride
#define GB (SN * HSF)     // graph-B offset in h
#define OB (SN * OSF)     // graph-B offset in out

typedef unsigned long long ull;

__device__ __forceinline__ ull pk2(float x, float y) {
    ull r; asm("mov.b64 %0, {%1,%2};" : "=l"(r) : "f"(x), "f"(y)); return r;
}
__device__ __forceinline__ float2 upk2(ull a) {
    float2 v; asm("mov.b64 {%0,%1}, %2;" : "=f"(v.x), "=f"(v.y) : "l"(a)); return v;
}
__device__ __forceinline__ ull ffma2(ull a, ull b, ull c) {
    ull d; asm("fma.rn.f32x2 %0, %1, %2, %3;" : "=l"(d) : "l"(a), "l"(b), "l"(c)); return d;
}
__device__ __forceinline__ ull fadd2(ull a, ull b) {
    ull d; asm("add.rn.f32x2 %0, %1, %2;" : "=l"(d) : "l"(a), "l"(b)); return d;
}

__device__ float g_pooled[NG * 72];

struct __align__(16) Smem {
    // 16B-aligned weight arrays first (sizes multiples of 16B)
    float wc3[36 * 72];
    float wr2[36 * 72];
    float wc2[18 * 36];
    float wr1[18 * 36];
    // small arrays (even float counts -> 8B alignment preserved)
    float E1[56];             // emb @ wc1, rows of 18
    float embs[56];
    float bc1[18], bc2[36], bc3[72];
    float br1[36], br2[72];
    float g1v[18], be1v[18], a1v[18];
    float g2v[36], be2v[36], a2v[36];
    float g3v[72], be3v[72], a3v[72];
    float redP[192], redQ[192];
    float redS[72], redC[72];     // [0:36) graph A, [36:72) graph B
    float dis[170];
    float h[2 * SN * HSF];
    float out[2 * SN * OSF];
};

__device__ __forceinline__ void cp_sm(float* dst, const float* src, int n, int t) {
    for (int i = t; i < n; i += NT) dst[i] = src[i];
}

// gather W features from own row + 6 neighbors -> dst (scaled by disn^2/disn*dnb)
template<int W>
__device__ __forceinline__ void gatherW(const float* base, const float* own, float* dst,
                                        const int* nbF, const float* dnb, float disn) {
    #pragma unroll 2
    for (int k = 0; k < W; k++) {
        float a = own[k] * disn;
        #pragma unroll
        for (int j = 0; j < 6; j++) a += base[nbF[j] + k] * dnb[j];
        dst[k] = a * disn;
    }
}

// acc[0:18) += inA (scalar k) * Wrow ; acc[18:36) += inB * Wrow  (36-wide output rows)
template<int K, int RS>
__device__ __forceinline__ void mm2(const float* W0, const float* inA, const float* inB, ull* acc) {
    #pragma unroll 2
    for (int k = 0; k < K; k++) {
        const float aA = inA[k], aB = inB[k];
        const ull qA = pk2(aA, aA), qB = pk2(aB, aB);
        const ulonglong2* w = (const ulonglong2*)(W0 + k * RS);
        #pragma unroll
        for (int jv = 0; jv < 9; jv++) {
            ulonglong2 ww = w[jv];
            acc[2 * jv]      = ffma2(qA, ww.x, acc[2 * jv]);
            acc[2 * jv + 1]  = ffma2(qA, ww.y, acc[2 * jv + 1]);
            acc[18 + 2 * jv]     = ffma2(qB, ww.x, acc[18 + 2 * jv]);
            acc[18 + 2 * jv + 1] = ffma2(qB, ww.y, acc[18 + 2 * jv + 1]);
        }
    }
}

// stats over out arrays for both graphs: A threads [0,Wf*NS), B threads [96,96+Wf*NS)
__device__ __forceinline__ void statpair(Smem& sm, int t, int Wf, int NS) {
    if (t < Wf * NS) {
        const int f = t % Wf, sI = t / Wf;
        float s = 0.f, s2 = 0.f;
        const float* pp = sm.out + f;
        for (int n = sI; n < SN; n += NS) { float v = pp[n * OSF]; s += v; s2 = fmaf(v, v, s2); }
        sm.redP[t] = s; sm.redQ[t] = s2;
    } else if (t >= 96 && t < 96 + Wf * NS) {
        const int u = t - 96, f = u % Wf, sI = u / Wf;
        float s = 0.f, s2 = 0.f;
        const float* pp = sm.out + OB + f;
        for (int n = sI; n < SN; n += NS) { float v = pp[n * OSF]; s += v; s2 = fmaf(v, v, s2); }
        sm.redP[t] = s; sm.redQ[t] = s2;
    }
}

__device__ __forceinline__ void scpair(Smem& sm, int t, int Wf, int NS,
                                       const float* gv, const float* bev, const float* av, int poff) {
    const float invS = 1.0f / (float)SN;
    if (t < Wf) {
        float s = 0.f, s2 = 0.f;
        for (int i = 0; i < NS; i++) { s += sm.redP[t + i * Wf]; s2 += sm.redQ[t + i * Wf]; }
        float m = s * invS, af = av[poff + t];
        float var = s2 * invS - m * m * af * (2.0f - af);
        float S = gv[poff + t] * rsqrtf(var + EPSV);
        sm.redS[t] = S; sm.redC[t] = bev[poff + t] - af * m * S;
    } else if (t >= 96 && t < 96 + Wf) {
        const int f = t - 96;
        float s = 0.f, s2 = 0.f;
        for (int i = 0; i < NS; i++) { s += sm.redP[96 + f + i * Wf]; s2 += sm.redQ[96 + f + i * Wf]; }
        float m = s * invS, af = av[poff + f];
        float var = s2 * invS - m * m * af * (2.0f - af);
        float S = gv[poff + f] * rsqrtf(var + EPSV);
        sm.redS[36 + f] = S; sm.redC[36 + f] = bev[poff + f] - af * m * S;
    }
}

__global__ void __launch_bounds__(NT) gnn_kernel(
    const int* __restrict__ x,
    const float* __restrict__ emb,
    const float* __restrict__ wc1, const float* __restrict__ bc1,
    const float* __restrict__ wc2, const float* __restrict__ bc2,
    const float* __restrict__ wc3, const float* __restrict__ bc3,
    const float* __restrict__ wr1, const float* __restrict__ br1,
    const float* __restrict__ wr2, const float* __restrict__ br2,
    const float* __restrict__ g1, const float* __restrict__ be1, const float* __restrict__ a1,
    const float* __restrict__ g2, const float* __restrict__ be2, const float* __restrict__ a2,
    const float* __restrict__ g3, const float* __restrict__ be3, const float* __restrict__ a3)
{
    extern __shared__ char smraw[];
    Smem& sm = *reinterpret_cast<Smem*>(smraw);
    const int t = threadIdx.x;
    const bool isNode = (t < SN);

    // ---- stage weights/params once ----
    cp_sm(sm.wc3, wc3, 36 * 72, t);
    cp_sm(sm.wr2, wr2, 36 * 72, t);
    cp_sm(sm.wc2, wc2, 18 * 36, t);
    cp_sm(sm.wr1, wr1, 18 * 36, t);
    cp_sm(sm.bc1, bc1, 18, t);  cp_sm(sm.bc2, bc2, 36, t);  cp_sm(sm.bc3, bc3, 72, t);
    cp_sm(sm.br1, br1, 36, t);  cp_sm(sm.br2, br2, 72, t);
    cp_sm(sm.g1v, g1, 18, t);   cp_sm(sm.be1v, be1, 18, t); cp_sm(sm.a1v, a1, 18, t);
    cp_sm(sm.g2v, g2, 36, t);   cp_sm(sm.be2v, be2, 36, t); cp_sm(sm.a2v, a2, 36, t);
    cp_sm(sm.g3v, g3, 72, t);   cp_sm(sm.be3v, be3, 72, t); cp_sm(sm.a3v, a3, 72, t);
    cp_sm(sm.embs, emb, 3 * 18, t);

    // E1 = emb @ wc1  (3x18)
    if (t < 54) {
        const int e = t / 18, j = t % 18;
        float s = 0.f;
        #pragma unroll
        for (int k = 0; k < 18; k++) s += emb[e * 18 + k] * wc1[k * 18 + j];
        sm.E1[e * 18 + j] = s;
    }

    // ---- analytic hex topology ----
    int nbF[6], nbi[6];
    float dnb[6];
    float disn = 0.f;
    if (isNode) {
        const int r = t / NBOARD, c = t % NBOARD;
        const int drr[6] = { -1, 1, 0, 0, -1, 1 };
        const int dcc[6] = { 0, 0, -1, 1, 1, -1 };
        int deg = 1;
        #pragma unroll
        for (int j = 0; j < 6; j++) {
            int rr = r + drr[j], cc = c + dcc[j];
            if (rr >= 0 && rr < NBOARD && cc >= 0 && cc < NBOARD) { nbi[j] = rr * NBOARD + cc; deg++; }
            else nbi[j] = t;
            nbF[j] = nbi[j] * HSF;
        }
        disn = rsqrtf((float)deg);
        sm.dis[t] = disn;
    }
    __syncthreads();
    if (isNode) {
        #pragma unroll
        for (int j = 0; j < 6; j++) dnb[j] = (nbi[j] == t) ? 0.f : sm.dis[nbi[j]];
    }
    __syncthreads();

    float* const hA = sm.h + t * HSF;
    float* const hB = sm.h + GB + t * HSF;
    float* const oA = sm.out + t * OSF;
    float* const oB = sm.out + OB + t * OSF;

    // =================== persistent loop over graph pairs ===================
    for (int p = blockIdx.x; p < NG / 2; p += GRID) {
        const int gA = 2 * p, gB2 = 2 * p + 1;

        // ---- lookup: h <- E1[x], h0 kept in regs ----
        ull h0A[9], h0B[9];
        if (isNode) {
            const int xa = x[gA * SN + t];
            const int xb = x[gB2 * SN + t];
            const ull* ea = (const ull*)&sm.embs[xa * 18];
            const ull* eb = (const ull*)&sm.embs[xb * 18];
            const ull* fa = (const ull*)&sm.E1[xa * 18];
            const ull* fb = (const ull*)&sm.E1[xb * 18];
            ull* ha = (ull*)hA; ull* hb = (ull*)hB;
            #pragma unroll
            for (int i = 0; i < 9; i++) { h0A[i] = ea[i]; h0B[i] = eb[i]; ha[i] = fa[i]; hb[i] = fb[i]; }
        }
        __syncthreads();

        // ================= Layer 1: conv = gather(E1x) + bc1 ================
        if (isNode) {
            #pragma unroll 2
            for (int k = 0; k < 18; k++) {
                float a = hA[k] * disn;
                #pragma unroll
                for (int j = 0; j < 6; j++) a += sm.h[nbF[j] + k] * dnb[j];
                oA[k] = a * disn + sm.bc1[k];
            }
            #pragma unroll 2
            for (int k = 0; k < 18; k++) {
                float a = hB[k] * disn;
                #pragma unroll
                for (int j = 0; j < 6; j++) a += sm.h[GB + nbF[j] + k] * dnb[j];
                oB[k] = a * disn + sm.bc1[k];
            }
        }
        __syncthreads();
        statpair(sm, t, 18, 5);
        __syncthreads();
        scpair(sm, t, 18, 5, sm.g1v, sm.be1v, sm.a1v, 0);
        __syncthreads();
        if (isNode) {
            ull* ha = (ull*)hA; ull* hb = (ull*)hB;
            const ull* ouA = (const ull*)oA; const ull* ouB = (const ull*)oB;
            const ull* SuA = (const ull*)sm.redS;        const ull* CuA = (const ull*)sm.redC;
            const ull* SuB = (const ull*)&sm.redS[36];   const ull* CuB = (const ull*)&sm.redC[36];
            #pragma unroll
            for (int i = 0; i < 9; i++) {
                ha[i] = fadd2(ffma2(ouA[i], SuA[i], CuA[i]), h0A[i]);
                hb[i] = fadd2(ffma2(ouB[i], SuB[i], CuB[i]), h0B[i]);
            }
        }
        __syncthreads();

        // ================= Layer 2 (18->36) =================================
        ull accR[36];
        if (isNode) {
            // gather -> agg region
            gatherW<18>(sm.h, hA, hA + AOFF, nbF, dnb, disn);
            gatherW<18>(sm.h + GB, hB, hB + AOFF, nbF, dnb, disn);
            // conv: both graphs share weight rows
            ull acc[36];
            const ull* b2 = (const ull*)sm.bc2;
            #pragma unroll
            for (int i = 0; i < 18; i++) { acc[i] = b2[i]; acc[18 + i] = b2[i]; }
            mm2<18, 36>(sm.wc2, hA + AOFF, hB + AOFF, acc);
            ull* ouA = (ull*)oA; ull* ouB = (ull*)oB;
            #pragma unroll
            for (int i = 0; i < 18; i++) { ouA[i] = acc[i]; ouB[i] = acc[18 + i]; }
            // resid: kept in regs through stats
            const ull* r1 = (const ull*)sm.br1;
            #pragma unroll
            for (int i = 0; i < 18; i++) { accR[i] = r1[i]; accR[18 + i] = r1[i]; }
            mm2<18, 36>(sm.wr1, hA, hB, accR);
        }
        __syncthreads();
        statpair(sm, t, 36, 2);
        __syncthreads();
        scpair(sm, t, 36, 2, sm.g2v, sm.be2v, sm.a2v, 0);
        __syncthreads();
        if (isNode) {
            ull* ha = (ull*)hA; ull* hb = (ull*)hB;
            const ull* ouA = (const ull*)oA; const ull* ouB = (const ull*)oB;
            const ull* SuA = (const ull*)sm.redS;        const ull* CuA = (const ull*)sm.redC;
            const ull* SuB = (const ull*)&sm.redS[36];   const ull* CuB = (const ull*)&sm.redC[36];
            #pragma unroll
            for (int i = 0; i < 18; i++) {
                ha[i] = fadd2(ffma2(ouA[i], SuA[i], CuA[i]), accR[i]);
                hb[i] = fadd2(ffma2(ouB[i], SuB[i], CuB[i]), accR[18 + i]);
            }
        }
        __syncthreads();

        // ================= Layer 3 (36->72), two j-halves ===================
        if (isNode) {
            gatherW<36>(sm.h, hA, hA + AOFF, nbF, dnb, disn);
            gatherW<36>(sm.h + GB, hB, hB + AOFF, nbF, dnb, disn);
        }
        // no barrier needed: agg written/read by the same thread

        #pragma unroll 1
        for (int hf = 0; hf < 2; hf++) {
            // conv half
            if (isNode) {
                ull acc[36];
                const ull* b3 = (const ull*)&sm.bc3[36 * hf];
                #pragma unroll
                for (int i = 0; i < 18; i++) { acc[i] = b3[i]; acc[18 + i] = b3[i]; }
                mm2<36, 72>(sm.wc3 + 36 * hf, hA + AOFF, hB + AOFF, acc);
                ull* ouA = (ull*)oA; ull* ouB = (ull*)oB;
                #pragma unroll
                for (int i = 0; i < 18; i++) { ouA[i] = acc[i]; ouB[i] = acc[18 + i]; }
            }
            __syncthreads();
            statpair(sm, t, 36, 2);
            __syncthreads();
            scpair(sm, t, 36, 2, sm.g3v, sm.be3v, sm.a3v, 36 * hf);
            __syncthreads();
            // resid half + apply (final into out)
            if (isNode) {
                const ull* r2 = (const ull*)&sm.br2[36 * hf];
                #pragma unroll
                for (int i = 0; i < 18; i++) { accR[i] = r2[i]; accR[18 + i] = r2[i]; }
                mm2<36, 72>(sm.wr2 + 36 * hf, hA, hB, accR);
                ull* ouA = (ull*)oA; ull* ouB = (ull*)oB;
                const ull* SuA = (const ull*)sm.redS;        const ull* CuA = (const ull*)sm.redC;
                const ull* SuB = (const ull*)&sm.redS[36];   const ull* CuB = (const ull*)&sm.redC[36];
                #pragma unroll
                for (int i = 0; i < 18; i++) {
                    ouA[i] = fadd2(ffma2(ouA[i], SuA[i], CuA[i]), accR[i]);
                    ouB[i] = fadd2(ffma2(ouB[i], SuB[i], CuB[i]), accR[18 + i]);
                }
            }
            __syncthreads();
            // pool half: partial then final
            if (t < 72) {
                const int f = t % 36, sI = t / 36;
                float m = -INFINITY;
                const float* pp = sm.out + f;
                for (int n = sI; n < SN; n += 2) m = fmaxf(m, pp[n * OSF]);
                sm.redP[t] = m;
            } else if (t >= 96 && t < 168) {
                const int u = t - 96, f = u % 36, sI = u / 36;
                float m = -INFINITY;
                const float* pp = sm.out + OB + f;
                for (int n = sI; n < SN; n += 2) m = fmaxf(m, pp[n * OSF]);
                sm.redP[t] = m;
            }
            __syncthreads();
            if (t < 36) g_pooled[gA * 72 + 36 * hf + t] = fmaxf(sm.redP[t], sm.redP[t + 36]);
            else if (t >= 96 && t < 132) {
                const int f = t - 96;
                g_pooled[gB2 * 72 + 36 * hf + f] = fmaxf(sm.redP[96 + f], sm.redP[96 + f + 36]);
            }
            __syncthreads();
        }
    }
}

// ---------------------------------------------------------------------------
// MLP (R3/R5/R8 exact, 35.9us): TM=8, grid 256, 512 threads, split-k z2.
// ---------------------------------------------------------------------------
struct __align__(16) MSmem {
    ull rowsT[72][5];
    ull z1T[512][5];
    ull z2P[256][5];
    ull z2T[256][5];
};

__global__ void __launch_bounds__(512, 2) mlp_kernel(
    const float* __restrict__ wf1, const float* __restrict__ bf1,
    const float* __restrict__ wf2, const float* __restrict__ bf2,
    const float* __restrict__ wm, const float* __restrict__ bm,
    const float* __restrict__ wl, const float* __restrict__ bl,
    float* __restrict__ out)
{
    extern __shared__ char smraw[];
    MSmem& sm = *reinterpret_cast<MSmem*>(smraw);
    const int tid = threadIdx.x;
    const int r0 = blockIdx.x * 8;

    {
        float* rf = (float*)sm.rowsT;
        for (int i = tid; i < 8 * 72; i += 512) {
            const int k = i / 8, r = i % 8;
            rf[k * 10 + r] = g_pooled[(r0 + r) * 72 + k];
        }
    }
    __syncthreads();

    {
        const int j = tid;
        const float b = __ldg(bf1 + j);
        ull acc[4];
        #pragma unroll
        for (int i = 0; i < 4; i++) acc[i] = pk2(b, b);
        #pragma unroll 8
        for (int k = 0; k < 72; k++) {
            const float w = __ldg(wf1 + k * 512 + j);
            const ull ww = pk2(w, w);
            const ull* rw = sm.rowsT[k];
            #pragma unroll
            for (int i = 0; i < 4; i++) acc[i] = ffma2(ww, rw[i], acc[i]);
        }
        #pragma unroll
        for (int i = 0; i < 4; i++) {
            float2 v = upk2(acc[i]);
            sm.z1T[j][i] = pk2(fmaxf(v.x, 0.f), fmaxf(v.y, 0.f));
        }
    }
    __syncthreads();

    {
        const int jj = tid & 255, half = tid >> 8;
        ull acc[4];
        if (half == 0) {
            const float b = __ldg(bf2 + jj);
            #pragma unroll
            for (int i = 0; i < 4; i++) acc[i] = pk2(b, b);
        } else {
            #pragma unroll
            for (int i = 0; i < 4; i++) acc[i] = 0ull;
        }
        const int k0 = half * 256;
        #pragma unroll 8
        for (int kk = 0; kk < 256; kk++) {
            const int k = k0 + kk;
            const float w = __ldg(wf2 + k * 256 + jj);
            const ull ww = pk2(w, w);
            const ull* zw = sm.z1T[k];
            #pragma unroll
            for (int i = 0; i < 4; i++) acc[i] = ffma2(ww, zw[i], acc[i]);
        }
        if (half == 1) {
            #pragma unroll
            for (int i = 0; i < 4; i++) sm.z2P[jj][i] = acc[i];
        }
        __syncthreads();
        if (half == 0) {
            #pragma unroll
            for (int i = 0; i < 4; i++) {
                float2 v = upk2(fadd2(acc[i], sm.z2P[jj][i]));
                sm.z2T[jj][i] = pk2(fmaxf(v.x, 0.f), fmaxf(v.y, 0.f));
            }
        }
        __syncthreads();
    }

    {
        const int w = tid >> 5, lane = tid & 31;
        if (w < 8) {
            const int rp = w >> 1, hi = w & 1;
            float smv = 0.f, slv = 0.f;
            #pragma unroll 4
            for (int k = lane; k < 256; k += 32) {
                float2 v2 = upk2(sm.z2T[k][rp]);
                const float v = hi ? v2.y : v2.x;
                smv = fmaf(v, __ldg(wm + k), smv);
                slv = fmaf(v, __ldg(wl + k), slv);
            }
            #pragma unroll
            for (int o = 16; o > 0; o >>= 1) {
                smv += __shfl_xor_sync(0xffffffffu, smv, o);
                slv += __shfl_xor_sync(0xffffffffu, slv, o);
            }
            if (lane == 0) {
                out[r0 + w] = smv + __ldg(bm);
                const float ls = tanhf(slv + __ldg(bl));
                out[NG + r0 + w] = LSMIN + 0.5f * (LSMAX - LSMIN) * (ls + 1.0f);
            }
        }
    }
}

// ---------------------------------------------------------------------------
extern "C" void kernel_launch(void* const* d_in, const int* in_sizes, int n_in,
                              void* d_out, int out_size)
{
    const int*   x    = (const int*)d_in[0];
    const float* emb  = (const float*)d_in[2];
    const float* wc1  = (const float*)d_in[3];
    const float* bc1  = (const float*)d_in[4];
    const float* wc2  = (const float*)d_in[5];
    const float* bc2  = (const float*)d_in[6];
    const float* wc3  = (const float*)d_in[7];
    const float* bc3  = (const float*)d_in[8];
    const float* wr1  = (const float*)d_in[9];
    const float* br1  = (const float*)d_in[10];
    const float* wr2  = (const float*)d_in[11];
    const float* br2  = (const float*)d_in[12];
    const float* g1   = (const float*)d_in[13];
    const float* be1  = (const float*)d_in[14];
    const float* a1   = (const float*)d_in[15];
    const float* g2   = (const float*)d_in[16];
    const float* be2  = (const float*)d_in[17];
    const float* a2   = (const float*)d_in[18];
    const float* g3   = (const float*)d_in[19];
    const float* be3  = (const float*)d_in[20];
    const float* a3   = (const float*)d_in[21];
    const float* wf1  = (const float*)d_in[22];
    const float* bf1  = (const float*)d_in[23];
    const float* wf2  = (const float*)d_in[24];
    const float* bf2  = (const float*)d_in[25];
    const float* wm   = (const float*)d_in[26];
    const float* bm   = (const float*)d_in[27];
    const float* wl   = (const float*)d_in[28];
    const float* bl   = (const float*)d_in[29];
    float* out = (float*)d_out;

    cudaFuncSetAttribute(gnn_kernel, cudaFuncAttributeMaxDynamicSharedMemorySize,
                         (int)sizeof(Smem));
    cudaFuncSetAttribute(mlp_kernel, cudaFuncAttributeMaxDynamicSharedMemorySize,
                         (int)sizeof(MSmem));

    gnn_kernel<<<GRID, NT, sizeof(Smem)>>>(
        x, emb, wc1, bc1, wc2, bc2, wc3, bc3, wr1, br1, wr2, br2,
        g1, be1, a1, g2, be2, a2, g3, be3, a3);

    mlp_kernel<<<NG / 8, 512, sizeof(MSmem)>>>(
        wf1, bf1, wf2, bf2, wm, bm, wl, bl, out);
}